// round 7
// baseline (speedup 1.0000x reference)
#include <cuda_runtime.h>

#define NB 32
#define NL 100
#define NT (NB*NL)      // 3200 tokens
#define ND 200
#define INDIM 360
#define EMBD 300
#define POSD 30
#define NERD 30
#define NREL 40

#define BM 32           // tokens per block tile (GEMM)
#define BN 40           // outputs per block tile (GEMM): 5*40 = 200 exact
#define KC 16           // k chunk
#define GT 160          // gemm threads
#define AGG_ROWS 4      // l rows per agg block
#define MH 50           // m per half (two warp-groups split the m range)

typedef unsigned long long ull;

__device__ float g_xa[NT*INDIM];
__device__ float g_xb[NT*ND];
__device__ float g_z[NT*ND];
__device__ float g_invden[NT];

__device__ __forceinline__ void fma2(ull& acc, ull a, ull b) {
    asm("fma.rn.f32x2 %0, %1, %2, %0;" : "+l"(acc) : "l"(a), "l"(b));
}
__device__ __forceinline__ ull add2(ull a, ull b) {
    ull r;
    asm("add.rn.f32x2 %0, %1, %2;" : "=l"(r) : "l"(a), "l"(b));
    return r;
}

// ---------------------------------------------------------------------------
// denom + mask
// ---------------------------------------------------------------------------
__global__ void denom_mask_kernel(const int* __restrict__ adj,
                                  float* __restrict__ out_mask,
                                  int write_mask) {
    __shared__ int A[NL*NL];     // 40 KB
    int b = blockIdx.x;
    int tid = threadIdx.x;
    const int* src = adj + b*NL*NL;
    for (int i = tid; i < NL*NL; i += blockDim.x) A[i] = src[i];
    __syncthreads();
    if (tid < NL) {
        int rc = 0, cc = 0;
        #pragma unroll 4
        for (int m = 0; m < NL; m++) {
            rc += (A[tid*NL + m] != 0);
            cc += (A[m*NL + tid] != 0);
        }
        g_invden[b*NL + tid] = 1.0f / (float)(rc + 1);
        if (write_mask)
            out_mask[b*NL + tid] = (rc + cc == 0) ? 1.0f : 0.0f;
    }
}

// ---------------------------------------------------------------------------
// Embedding gather: one block per token
// ---------------------------------------------------------------------------
__global__ void gather_kernel(const int* __restrict__ words,
                              const int* __restrict__ pos,
                              const int* __restrict__ ner,
                              const float* __restrict__ emb,
                              const float* __restrict__ pos_emb,
                              const float* __restrict__ ner_emb,
                              float* __restrict__ xout) {
    int tok = blockIdx.x;
    int k = threadIdx.x;
    if (k >= INDIM) return;
    float v;
    if (k < EMBD)            v = emb[words[tok]*EMBD + k];
    else if (k < EMBD+POSD)  v = pos_emb[pos[tok]*POSD + (k - EMBD)];
    else                     v = ner_emb[ner[tok]*NERD + (k - EMBD - POSD)];
    xout[tok*INDIM + k] = v;
}

// ---------------------------------------------------------------------------
// Double-buffered SGEMM: C[M x 200] = A[M x K] . B[200 x K]^T
// Block tile 32x40, 160 threads, 2x4 per thread. 200 = 5*40: no padded-column
// waste. One __syncthreads per k-chunk; loads of chunk c+1 overlap compute.
// MODE 0: C = acc + bias[j]
// MODE 1: C = relu((acc + 2*bias[j]) * invden[t])
// ---------------------------------------------------------------------------
template<int K, int MODE>
__global__ __launch_bounds__(GT) void gemm_kernel(const float* __restrict__ A,
                                                  const float* __restrict__ B,
                                                  const float* __restrict__ bias,
                                                  float* __restrict__ C) {
    const int NC = (K + KC - 1) / KC;
    __shared__ __align__(16) float As[2][KC][BM+4];   // 16 x 36
    __shared__ __align__(16) float Bs[2][KC][BN+8];   // 16 x 48
    int tid = threadIdx.x;
    int tx = tid & 15, ty = tid >> 4;                 // ty 0..9
    int t0 = blockIdx.x * BM;
    int j0 = blockIdx.y * BN;

    int lkk = tid & 15;
    int lrowB = tid >> 4;        // 0..9
    int lrowA = (tid & 127) >> 4; // 0..7 (only tid<128 loads A)
    bool loadsA = tid < 128;

    float rA[4], rB[4];

    // --- preload chunk 0 ---
    if (loadsA) {
        #pragma unroll
        for (int it = 0; it < 4; it++)
            rA[it] = A[(t0 + lrowA + it*8)*K + lkk];
    }
    #pragma unroll
    for (int it = 0; it < 4; it++)
        rB[it] = B[(j0 + lrowB + it*10)*K + lkk];
    if (loadsA) {
        #pragma unroll
        for (int it = 0; it < 4; it++) As[0][lkk][lrowA + it*8] = rA[it];
    }
    #pragma unroll
    for (int it = 0; it < 4; it++) Bs[0][lkk][lrowB + it*10] = rB[it];
    __syncthreads();

    float acc[2][4];
    #pragma unroll
    for (int i = 0; i < 2; i++)
        #pragma unroll
        for (int j = 0; j < 4; j++) acc[i][j] = 0.f;

    for (int c = 0; c < NC; c++) {
        int cur = c & 1;
        if (c + 1 < NC) {
            int k = (c + 1) * KC + lkk;
            if (loadsA) {
                #pragma unroll
                for (int it = 0; it < 4; it++)
                    rA[it] = (k < K) ? A[(t0 + lrowA + it*8)*K + k] : 0.f;
            }
            #pragma unroll
            for (int it = 0; it < 4; it++)
                rB[it] = (k < K) ? B[(j0 + lrowB + it*10)*K + k] : 0.f;
        }
        #pragma unroll
        for (int kk = 0; kk < KC; kk++) {
            float2 a = *(const float2*)&As[cur][kk][2*tx];
            float4 b = *(const float4*)&Bs[cur][kk][4*ty];
            acc[0][0] += a.x*b.x; acc[0][1] += a.x*b.y; acc[0][2] += a.x*b.z; acc[0][3] += a.x*b.w;
            acc[1][0] += a.y*b.x; acc[1][1] += a.y*b.y; acc[1][2] += a.y*b.z; acc[1][3] += a.y*b.w;
        }
        if (c + 1 < NC) {
            int nxt = cur ^ 1;
            if (loadsA) {
                #pragma unroll
                for (int it = 0; it < 4; it++) As[nxt][lkk][lrowA + it*8] = rA[it];
            }
            #pragma unroll
            for (int it = 0; it < 4; it++) Bs[nxt][lkk][lrowB + it*10] = rB[it];
        }
        __syncthreads();
    }

    int tbase = t0 + 2*tx;
    int jbase = j0 + 4*ty;       // always fully in-range: 200 = 5*40
    #pragma unroll
    for (int i = 0; i < 2; i++) {
        int tok = tbase + i;
        float inv = (MODE == 1) ? g_invden[tok] : 0.f;
        float4 v;
        if (MODE == 0) {
            v.x = acc[i][0] + bias[jbase];
            v.y = acc[i][1] + bias[jbase+1];
            v.z = acc[i][2] + bias[jbase+2];
            v.w = acc[i][3] + bias[jbase+3];
        } else {
            v.x = fmaxf((acc[i][0] + 2.f*bias[jbase])   * inv, 0.f);
            v.y = fmaxf((acc[i][1] + 2.f*bias[jbase+1]) * inv, 0.f);
            v.z = fmaxf((acc[i][2] + 2.f*bias[jbase+2]) * inv, 0.f);
            v.w = fmaxf((acc[i][3] + 2.f*bias[jbase+3]) * inv, 0.f);
        }
        *(float4*)&C[tok*ND + jbase] = v;
    }
}

// ---------------------------------------------------------------------------
// Aggregation: Z[b,l,d] = x[b,l,d] + sum_m E[adj[b,l,m], d] * x[b,m,d]
// 4 rows/block -> grid 800 (occupancy). 256 threads: two warp-groups split the
// m range; each thread owns a d-pair (f32x2). x loads software-pipelined in
// exact chunks of 5. Halves combined via smem partial buffer.
// ---------------------------------------------------------------------------
__global__ __launch_bounds__(256) void agg_kernel(const int* __restrict__ adj,
                                                  const float* __restrict__ dep,
                                                  const float* __restrict__ x,
                                                  float* __restrict__ z) {
    __shared__ __align__(16) float Es[NREL*ND];        // 32 KB
    __shared__ __align__(16) int adjs[NL*4];           // 1.6 KB
    __shared__ __align__(16) float part[AGG_ROWS][ND]; // 3.2 KB
    int tid = threadIdx.x;
    int b = blockIdx.y;
    int l0 = blockIdx.x * AGG_ROWS;

    for (int i = tid; i < NREL*ND; i += 256) Es[i] = dep[i];
    for (int i = tid; i < AGG_ROWS*NL; i += 256) {
        int j = i & 3, m = i >> 2;
        adjs[i] = adj[(b*NL + l0 + j)*NL + m] * (ND*4);
    }
    __syncthreads();

    int dp = tid & 127;
    int mh = tid >> 7;           // which m-half
    bool active = dp < ND/2;

    ull acc[AGG_ROWS];
    if (active) {
        const char* ep = (const char*)Es + 8*dp;
        const float* xb = x + b*NL*ND + 2*dp + mh*MH*ND;
        const int*  ap = adjs + mh*MH*4;

        if (mh == 0) {
            #pragma unroll
            for (int i = 0; i < AGG_ROWS; i++)
                acc[i] = *(const ull*)&x[(b*NL + l0 + i)*ND + 2*dp];
        } else {
            #pragma unroll
            for (int i = 0; i < AGG_ROWS; i++) acc[i] = 0ull;
        }

        // prefetch pipeline: exact chunks of 5 (50 = 10 x 5)
        ull xv[5];
        #pragma unroll
        for (int s = 0; s < 5; s++) xv[s] = *(const ull*)(xb + s*ND);

        #pragma unroll 1
        for (int m = 0; m < MH; m += 5) {
            ull cv[5];
            #pragma unroll
            for (int s = 0; s < 5; s++) cv[s] = xv[s];
            if (m + 5 < MH) {
                #pragma unroll
                for (int s = 0; s < 5; s++)
                    xv[s] = *(const ull*)(xb + (m + 5 + s)*ND);
            }
            #pragma unroll
            for (int s = 0; s < 5; s++) {
                const int4 r03 = *(const int4*)&ap[(m+s)*4];
                fma2(acc[0], *(const ull*)(ep + r03.x), cv[s]);
                fma2(acc[1], *(const ull*)(ep + r03.y), cv[s]);
                fma2(acc[2], *(const ull*)(ep + r03.z), cv[s]);
                fma2(acc[3], *(const ull*)(ep + r03.w), cv[s]);
            }
        }

        if (mh == 1) {
            #pragma unroll
            for (int i = 0; i < AGG_ROWS; i++)
                *(ull*)&part[i][2*dp] = acc[i];
        }
    }
    __syncthreads();
    if (active && mh == 0) {
        #pragma unroll
        for (int i = 0; i < AGG_ROWS; i++) {
            ull p = *(const ull*)&part[i][2*dp];
            *(ull*)&z[(b*NL + l0 + i)*ND + 2*dp] = add2(acc[i], p);
        }
    }
}

// ---------------------------------------------------------------------------
extern "C" void kernel_launch(void* const* d_in, const int* in_sizes, int n_in,
                              void* d_out, int out_size) {
    const int*   adj     = (const int*)  d_in[0];
    const int*   words   = (const int*)  d_in[1];
    const int*   pos     = (const int*)  d_in[2];
    const int*   ner     = (const int*)  d_in[3];
    const float* emb     = (const float*)d_in[4];
    const float* pos_emb = (const float*)d_in[5];
    const float* ner_emb = (const float*)d_in[6];
    const float* dep     = (const float*)d_in[7];
    const float* Wp      = (const float*)d_in[8];
    const float* bp      = (const float*)d_in[9];
    const float* W0      = (const float*)d_in[10];
    const float* b0      = (const float*)d_in[11];
    const float* W1      = (const float*)d_in[12];
    const float* b1      = (const float*)d_in[13];
    float* out = (float*)d_out;

    float *xa, *xb, *z;
    cudaGetSymbolAddress((void**)&xa, g_xa);
    cudaGetSymbolAddress((void**)&xb, g_xb);
    cudaGetSymbolAddress((void**)&z,  g_z);

    int write_mask = (out_size >= NT*ND + NT) ? 1 : 0;

    dim3 ggrid(NT/BM, ND/BN);                   // (100, 5) = 500 blocks
    dim3 agrid(NL/AGG_ROWS, NB);                // (25, 32) = 800 blocks

    denom_mask_kernel<<<NB, 256>>>(adj, out + NT*ND, write_mask);
    gather_kernel<<<NT, 384>>>(words, pos, ner, emb, pos_emb, ner_emb, xa);
    gemm_kernel<INDIM, 0><<<ggrid, GT>>>(xa, Wp, bp, xb);
    agg_kernel<<<agrid, 256>>>(adj, dep, xb, z);
    gemm_kernel<ND, 1><<<ggrid, GT>>>(z, W0, b0, xb);
    agg_kernel<<<agrid, 256>>>(adj, dep, xb, z);
    gemm_kernel<ND, 1><<<ggrid, GT>>>(z, W1, b1, out);
}